// round 8
// baseline (speedup 1.0000x reference)
#include <cuda_runtime.h>
#include <cstdint>

#define NJ      55
#define NWARPS  8                  // warps per CTA
#define TPB     (NWARPS * 32)      // 256 threads
#define VPW     64                 // vertices per warplet (2 per lane)
#define WWORDS  (VPW * NJ)         // 3520 floats = 14080 B per warp buffer
#define SE3_BYTES (NJ * 3 * 16)    // 2640 B
#define SMEM_BYTES (SE3_BYTES + NWARPS * WWORDS * 4)   // 2640 + 112640 = 115280 B
#define GRID    296                // 2 CTAs per SM (148 SMs)

// Packed f32x2 FMA: d = a*b + d  (Blackwell packed fp32 pipe)
#define FMA_F32X2(acc, a, b) \
    asm("fma.rn.f32x2 %0, %1, %2, %0;" : "+l"(acc) : "l"(a), "l"(b))

__device__ __forceinline__ void cp_async16(uint32_t s, const void* g) {
    asm volatile("cp.async.cg.shared.global [%0], [%1], 16;" :: "r"(s), "l"(g));
}
__device__ __forceinline__ void cp_async4(uint32_t s, const void* g) {
    asm volatile("cp.async.ca.shared.global [%0], [%1], 4;" :: "r"(s), "l"(g));
}
__device__ __forceinline__ void cp_commit() {
    asm volatile("cp.async.commit_group;");
}
__device__ __forceinline__ void cp_wait0() {
    asm volatile("cp.async.wait_group 0;" ::: "memory");
}

// Stage one 64-vertex warplet's weights (coalesced float4 cp.async), warp-scoped.
__device__ __forceinline__ void prefetch_warplet(const float* __restrict__ weights,
                                                 int n, int base, float* buf, int lane)
{
    int nf = (n - base) * NJ;
    if (nf > WWORDS) nf = WWORDS;
    const float* g = weights + (size_t)base * NJ;   // base = wt*64 -> base*55 div by 4 -> 16B aligned
    uint32_t s = (uint32_t)__cvta_generic_to_shared(buf);
    int n4 = nf >> 2;                               // 880 for a full warplet
    for (int i = lane; i < n4; i += 32)
        cp_async16(s + i * 16, g + i * 4);
    for (int i = (n4 << 2) + lane; i < nf; i += 32) // generic tail (not taken for this n)
        cp_async4(s + i * 4, g + i);
}

__global__ void __launch_bounds__(TPB)
lbs_kernel(const float* __restrict__ points,
           const float* __restrict__ weights,
           const float* __restrict__ SE3,
           float* __restrict__ out,
           int n, int nwt, int wstride)
{
    extern __shared__ __align__(16) float smem[];
    double2* sm   = (double2*)smem;                 // SE3 rows 0..2 as packed f32x2 pairs
    float*   wbuf = smem + SE3_BYTES / 4;           // 8 per-warp buffers follow

    const int tid  = threadIdx.x;
    const int wid  = tid >> 5;
    const int lane = tid & 31;

    // --- Stage SE3 once (rows 0..2 of each joint; each row is one float4) ---
    {
        const float4* g = (const float4*)SE3;
        for (int idx = tid; idx < NJ * 3; idx += TPB) {
            int j = idx / 3;
            int r = idx - j * 3;
            float4 v = g[j * 4 + r];
            *(float4*)(&sm[idx]) = v;
        }
    }
    __syncthreads();   // only block-wide sync in the kernel

    float* mybuf = wbuf + wid * WWORDS;
    const float* wrowA = mybuf + lane * NJ;          // stride 55 (odd) -> conflict-free LDS.32
    const float* wrowB = mybuf + (lane + 32) * NJ;

    // Per-warp independent pipeline over warplets; warps never resync.
    for (int wt = blockIdx.x * NWARPS + wid; wt < nwt; wt += wstride) {
        __syncwarp();   // all lanes done reading mybuf from the previous warplet

        const int base = wt * VPW;
        prefetch_warplet(weights, n, base, mybuf, lane);
        cp_commit();

        const int v0 = base + lane;
        const int v1 = base + 32 + lane;
        const bool has0 = (v0 < n);
        const bool has1 = (v1 < n);

        // Point loads fly while cp.asyncs are in flight
        float px0 = 0.f, py0 = 0.f, pz0 = 0.f, px1 = 0.f, py1 = 0.f, pz1 = 0.f;
        if (has0) {
            px0 = __ldg(&points[(size_t)v0 * 3 + 0]);
            py0 = __ldg(&points[(size_t)v0 * 3 + 1]);
            pz0 = __ldg(&points[(size_t)v0 * 3 + 2]);
        }
        if (has1) {
            px1 = __ldg(&points[(size_t)v1 * 3 + 0]);
            py1 = __ldg(&points[(size_t)v1 * 3 + 1]);
            pz1 = __ldg(&points[(size_t)v1 * 3 + 2]);
        }

        cp_wait0();
        __syncwarp();   // warplet visible to all lanes of this warp

        if (!has0) continue;

        // Packed accumulators for blended 3x4 matrices of both vertices
        unsigned long long a0 = 0ull, a1 = 0ull, a2 = 0ull, a3 = 0ull, a4 = 0ull, a5 = 0ull;
        unsigned long long b0 = 0ull, b1 = 0ull, b2 = 0ull, b3 = 0ull, b4 = 0ull, b5 = 0ull;

        #pragma unroll
        for (int j = 0; j < NJ; ++j) {
            float wA = wrowA[j];
            float wB = wrowB[j];
            unsigned long long wA2, wB2;
            asm("mov.b64 %0, {%1, %1};" : "=l"(wA2) : "r"(__float_as_uint(wA)));
            asm("mov.b64 %0, {%1, %1};" : "=l"(wB2) : "r"(__float_as_uint(wB)));

            double2 r0 = sm[j * 3 + 0];   // LDS.128 broadcast, shared by both vertices
            double2 r1 = sm[j * 3 + 1];
            double2 r2 = sm[j * 3 + 2];
            unsigned long long m01 = __double_as_longlong(r0.x);
            unsigned long long m23 = __double_as_longlong(r0.y);
            unsigned long long m45 = __double_as_longlong(r1.x);
            unsigned long long m67 = __double_as_longlong(r1.y);
            unsigned long long m89 = __double_as_longlong(r2.x);
            unsigned long long mAB = __double_as_longlong(r2.y);

            FMA_F32X2(a0, wA2, m01);  FMA_F32X2(b0, wB2, m01);
            FMA_F32X2(a1, wA2, m23);  FMA_F32X2(b1, wB2, m23);
            FMA_F32X2(a2, wA2, m45);  FMA_F32X2(b2, wB2, m45);
            FMA_F32X2(a3, wA2, m67);  FMA_F32X2(b3, wB2, m67);
            FMA_F32X2(a4, wA2, m89);  FMA_F32X2(b4, wB2, m89);
            FMA_F32X2(a5, wA2, mAB);  FMA_F32X2(b5, wB2, mAB);
        }

        // --- Vertex 0 epilogue ---
        {
            float A00, A01, A02, A03, A10, A11, A12, A13, A20, A21, A22, A23;
            asm("mov.b64 {%0, %1}, %2;" : "=f"(A00), "=f"(A01) : "l"(a0));
            asm("mov.b64 {%0, %1}, %2;" : "=f"(A02), "=f"(A03) : "l"(a1));
            asm("mov.b64 {%0, %1}, %2;" : "=f"(A10), "=f"(A11) : "l"(a2));
            asm("mov.b64 {%0, %1}, %2;" : "=f"(A12), "=f"(A13) : "l"(a3));
            asm("mov.b64 {%0, %1}, %2;" : "=f"(A20), "=f"(A21) : "l"(a4));
            asm("mov.b64 {%0, %1}, %2;" : "=f"(A22), "=f"(A23) : "l"(a5));
            out[(size_t)v0 * 3 + 0] = fmaf(A00, px0, fmaf(A01, py0, fmaf(A02, pz0, A03)));
            out[(size_t)v0 * 3 + 1] = fmaf(A10, px0, fmaf(A11, py0, fmaf(A12, pz0, A13)));
            out[(size_t)v0 * 3 + 2] = fmaf(A20, px0, fmaf(A21, py0, fmaf(A22, pz0, A23)));
        }

        // --- Vertex 1 epilogue ---
        if (has1) {
            float A00, A01, A02, A03, A10, A11, A12, A13, A20, A21, A22, A23;
            asm("mov.b64 {%0, %1}, %2;" : "=f"(A00), "=f"(A01) : "l"(b0));
            asm("mov.b64 {%0, %1}, %2;" : "=f"(A02), "=f"(A03) : "l"(b1));
            asm("mov.b64 {%0, %1}, %2;" : "=f"(A10), "=f"(A11) : "l"(b2));
            asm("mov.b64 {%0, %1}, %2;" : "=f"(A12), "=f"(A13) : "l"(b3));
            asm("mov.b64 {%0, %1}, %2;" : "=f"(A20), "=f"(A21) : "l"(b4));
            asm("mov.b64 {%0, %1}, %2;" : "=f"(A22), "=f"(A23) : "l"(b5));
            out[(size_t)v1 * 3 + 0] = fmaf(A00, px1, fmaf(A01, py1, fmaf(A02, pz1, A03)));
            out[(size_t)v1 * 3 + 1] = fmaf(A10, px1, fmaf(A11, py1, fmaf(A12, pz1, A13)));
            out[(size_t)v1 * 3 + 2] = fmaf(A20, px1, fmaf(A21, py1, fmaf(A22, pz1, A23)));
        }
    }
}

extern "C" void kernel_launch(void* const* d_in, const int* in_sizes, int n_in,
                              void* d_out, int out_size)
{
    const float* points  = (const float*)d_in[0];   // [n,3]
    const float* weights = (const float*)d_in[1];   // [n,55]
    const float* SE3     = (const float*)d_in[2];   // [55,4,4]
    float* out = (float*)d_out;

    int n = in_sizes[0] / 3;
    int nwt = (n + VPW - 1) / VPW;                  // 64-vertex warplets

    cudaFuncSetAttribute(lbs_kernel, cudaFuncAttributeMaxDynamicSharedMemorySize, SMEM_BYTES);

    int grid = GRID;
    int maxg = (nwt + NWARPS - 1) / NWARPS;
    if (grid > maxg) grid = maxg;
    int wstride = grid * NWARPS;
    lbs_kernel<<<grid, TPB, SMEM_BYTES>>>(points, weights, SE3, out, n, nwt, wstride);
}

// round 9
// speedup vs baseline: 1.0054x; 1.0054x over previous
#include <cuda_runtime.h>
#include <cstdint>

#define NJ      55
#define TPB     64                 // 2 warps per CTA
#define VPB     128                // vertices per tile (2 per thread)
#define HVERTS  64                 // vertices per half-tile
#define HWORDS  (HVERTS * NJ)      // 3520 floats = 14080 B per half buffer
#define NSLOT   3                  // ring of 3 half-buffers
#define SE3_BYTES (NJ * 3 * 16)    // 2640 B
#define SMEM_BYTES (NSLOT * HWORDS * 4 + SE3_BYTES)   // 42240 + 2640 = 44880 B
#define GRID    (148 * 5)          // 5 CTAs per SM

// Packed f32x2 FMA: d = a*b + d  (Blackwell packed fp32 pipe)
#define FMA_F32X2(acc, a, b) \
    asm("fma.rn.f32x2 %0, %1, %2, %0;" : "+l"(acc) : "l"(a), "l"(b))

__device__ __forceinline__ void cp_async16(uint32_t s, const void* g) {
    asm volatile("cp.async.cg.shared.global [%0], [%1], 16;" :: "r"(s), "l"(g));
}
__device__ __forceinline__ void cp_commit() {
    asm volatile("cp.async.commit_group;");
}
__device__ __forceinline__ void cp_wait1() {
    asm volatile("cp.async.wait_group 1;" ::: "memory");
}

// Stage one 64-vertex half-tile's weights (coalesced float4 cp.async).
// base = tile*VPB + half*HVERTS is a multiple of 64 -> base*55*4 bytes is 16B aligned.
__device__ __forceinline__ void prefetch_half(const float* __restrict__ weights,
                                              int n, int tile, int half,
                                              float* buf, int tid)
{
    int base = tile * VPB + half * HVERTS;
    int nf = (n - base) * NJ;
    if (nf <= 0) return;
    if (nf > HWORDS) nf = HWORDS;
    const float* g = weights + (size_t)base * NJ;
    uint32_t s = (uint32_t)__cvta_generic_to_shared(buf);
    int n4 = nf >> 2;                     // 880 for a full half (nf mult of 55*64 -> /4 exact)
    for (int i = tid; i < n4; i += TPB)
        cp_async16(s + i * 16, g + i * 4);
}

__global__ void __launch_bounds__(TPB)
lbs_kernel(const float* __restrict__ points,
           const float* __restrict__ weights,
           const float* __restrict__ SE3,
           float* __restrict__ out,
           int n, int ntiles)
{
    extern __shared__ __align__(16) float smem[];
    float*   ring = smem;                           // 3 half-buffers
    double2* sm   = (double2*)(smem + NSLOT * HWORDS);  // SE3 rows 0..2 as f32x2 pairs

    const int tid = threadIdx.x;

    // --- Stage SE3 once (rows 0..2 of each joint; each row is one float4) ---
    {
        const float4* g = (const float4*)SE3;
        for (int idx = tid; idx < NJ * 3; idx += TPB) {
            int j = idx / 3;
            int r = idx - j * 3;
            float4 v = g[j * 4 + r];
            *(float4*)(&sm[idx]) = v;
        }
    }

    // --- Prologue: both halves of the first tile ---
    const int first = blockIdx.x;
    const int stride = gridDim.x;
    prefetch_half(weights, n, first, 0, ring + 0 * HWORDS, tid);
    cp_commit();
    prefetch_half(weights, n, first, 1, ring + 1 * HWORDS, tid);
    cp_commit();

    int sA = 0, sB = 1;   // slots holding current tile's half0 / half1

    for (int tile = first; tile < ntiles; tile += stride) {
        const int sP = 3 - sA - sB;       // free slot
        const int next = tile + stride;

        // Prefetch next tile's half0 into the free slot (lookahead)
        if (next < ntiles) prefetch_half(weights, n, next, 0, ring + sP * HWORDS, tid);
        cp_commit();

        const int base = tile * VPB;
        const int v0 = base + tid;
        const int v1 = base + HVERTS + tid;
        const bool has0 = (v0 < n);
        const bool has1 = (v1 < n);

        // Point loads fly while cp.asyncs are in flight
        float px0 = 0.f, py0 = 0.f, pz0 = 0.f, px1 = 0.f, py1 = 0.f, pz1 = 0.f;
        if (has0) {
            px0 = __ldg(&points[(size_t)v0 * 3 + 0]);
            py0 = __ldg(&points[(size_t)v0 * 3 + 1]);
            pz0 = __ldg(&points[(size_t)v0 * 3 + 2]);
        }
        if (has1) {
            px1 = __ldg(&points[(size_t)v1 * 3 + 0]);
            py1 = __ldg(&points[(size_t)v1 * 3 + 1]);
            pz1 = __ldg(&points[(size_t)v1 * 3 + 2]);
        }

        cp_wait1();        // current tile's two halves complete (only newest group pending)
        __syncthreads();   // visibility across both warps (also orders SE3 staging, iter 0)

        if (has0) {
            // Packed accumulators for blended 3x4 matrices of both vertices
            unsigned long long a0 = 0ull, a1 = 0ull, a2 = 0ull, a3 = 0ull, a4 = 0ull, a5 = 0ull;
            unsigned long long b0 = 0ull, b1 = 0ull, b2 = 0ull, b3 = 0ull, b4 = 0ull, b5 = 0ull;

            const float* wrowA = ring + sA * HWORDS + tid * NJ;  // stride 55 -> conflict-free
            const float* wrowB = ring + sB * HWORDS + tid * NJ;

            #pragma unroll
            for (int j = 0; j < NJ; ++j) {
                float wA = wrowA[j];
                float wB = wrowB[j];
                unsigned long long wA2, wB2;
                asm("mov.b64 %0, {%1, %1};" : "=l"(wA2) : "r"(__float_as_uint(wA)));
                asm("mov.b64 %0, {%1, %1};" : "=l"(wB2) : "r"(__float_as_uint(wB)));

                double2 r0 = sm[j * 3 + 0];   // LDS.128 broadcast, shared by both vertices
                double2 r1 = sm[j * 3 + 1];
                double2 r2 = sm[j * 3 + 2];
                unsigned long long m01 = __double_as_longlong(r0.x);
                unsigned long long m23 = __double_as_longlong(r0.y);
                unsigned long long m45 = __double_as_longlong(r1.x);
                unsigned long long m67 = __double_as_longlong(r1.y);
                unsigned long long m89 = __double_as_longlong(r2.x);
                unsigned long long mAB = __double_as_longlong(r2.y);

                FMA_F32X2(a0, wA2, m01);  FMA_F32X2(b0, wB2, m01);
                FMA_F32X2(a1, wA2, m23);  FMA_F32X2(b1, wB2, m23);
                FMA_F32X2(a2, wA2, m45);  FMA_F32X2(b2, wB2, m45);
                FMA_F32X2(a3, wA2, m67);  FMA_F32X2(b3, wB2, m67);
                FMA_F32X2(a4, wA2, m89);  FMA_F32X2(b4, wB2, m89);
                FMA_F32X2(a5, wA2, mAB);  FMA_F32X2(b5, wB2, mAB);
            }

            // --- Vertex 0 epilogue ---
            {
                float A00, A01, A02, A03, A10, A11, A12, A13, A20, A21, A22, A23;
                asm("mov.b64 {%0, %1}, %2;" : "=f"(A00), "=f"(A01) : "l"(a0));
                asm("mov.b64 {%0, %1}, %2;" : "=f"(A02), "=f"(A03) : "l"(a1));
                asm("mov.b64 {%0, %1}, %2;" : "=f"(A10), "=f"(A11) : "l"(a2));
                asm("mov.b64 {%0, %1}, %2;" : "=f"(A12), "=f"(A13) : "l"(a3));
                asm("mov.b64 {%0, %1}, %2;" : "=f"(A20), "=f"(A21) : "l"(a4));
                asm("mov.b64 {%0, %1}, %2;" : "=f"(A22), "=f"(A23) : "l"(a5));
                out[(size_t)v0 * 3 + 0] = fmaf(A00, px0, fmaf(A01, py0, fmaf(A02, pz0, A03)));
                out[(size_t)v0 * 3 + 1] = fmaf(A10, px0, fmaf(A11, py0, fmaf(A12, pz0, A13)));
                out[(size_t)v0 * 3 + 2] = fmaf(A20, px0, fmaf(A21, py0, fmaf(A22, pz0, A23)));
            }

            // --- Vertex 1 epilogue ---
            if (has1) {
                float A00, A01, A02, A03, A10, A11, A12, A13, A20, A21, A22, A23;
                asm("mov.b64 {%0, %1}, %2;" : "=f"(A00), "=f"(A01) : "l"(b0));
                asm("mov.b64 {%0, %1}, %2;" : "=f"(A02), "=f"(A03) : "l"(b1));
                asm("mov.b64 {%0, %1}, %2;" : "=f"(A10), "=f"(A11) : "l"(b2));
                asm("mov.b64 {%0, %1}, %2;" : "=f"(A12), "=f"(A13) : "l"(b3));
                asm("mov.b64 {%0, %1}, %2;" : "=f"(A20), "=f"(A21) : "l"(b4));
                asm("mov.b64 {%0, %1}, %2;" : "=f"(A22), "=f"(A23) : "l"(b5));
                out[(size_t)v1 * 3 + 0] = fmaf(A00, px1, fmaf(A01, py1, fmaf(A02, pz1, A03)));
                out[(size_t)v1 * 3 + 1] = fmaf(A10, px1, fmaf(A11, py1, fmaf(A12, pz1, A13)));
                out[(size_t)v1 * 3 + 2] = fmaf(A20, px1, fmaf(A21, py1, fmaf(A22, pz1, A23)));
            }
        }

        __syncthreads();   // both warps done reading sA/sB before reusing sA below

        // Prefetch next tile's half1 into the slot just released (old sA)
        if (next < ntiles) prefetch_half(weights, n, next, 1, ring + sA * HWORDS, tid);
        cp_commit();

        // Next tile's halves live in (sP, old sA)
        int na = sP, nb = sA;
        sA = na; sB = nb;
    }
}

extern "C" void kernel_launch(void* const* d_in, const int* in_sizes, int n_in,
                              void* d_out, int out_size)
{
    const float* points  = (const float*)d_in[0];   // [n,3]
    const float* weights = (const float*)d_in[1];   // [n,55]
    const float* SE3     = (const float*)d_in[2];   // [55,4,4]
    float* out = (float*)d_out;

    int n = in_sizes[0] / 3;
    int ntiles = (n + VPB - 1) / VPB;

    cudaFuncSetAttribute(lbs_kernel, cudaFuncAttributeMaxDynamicSharedMemorySize, SMEM_BYTES);

    int grid = (ntiles < GRID) ? ntiles : GRID;
    lbs_kernel<<<grid, TPB, SMEM_BYTES>>>(points, weights, SE3, out, n, ntiles);
}

// round 10
// speedup vs baseline: 1.0876x; 1.0818x over previous
#include <cuda_runtime.h>
#include <cstdint>

#define NJ    55
#define TPB   64               // threads per block (2 warps)
#define VPB   128              // vertices per tile (2 per thread)
#define WBUF  (VPB * NJ)       // 7040 floats = 28160 B (single buffer)
#define GRID  (148 * 7)        // 7 CTAs per SM
#define SMEM_BYTES (WBUF * 4 + NJ * 3 * 16)   // 28160 + 2640 = 30800 B
#define TILE_LINES ((WBUF * 4 + 127) / 128)   // 220 x 128B lines per tile

// Packed f32x2 FMA: d = a*b + d  (Blackwell packed fp32 pipe)
#define FMA_F32X2(acc, a, b) \
    asm("fma.rn.f32x2 %0, %1, %2, %0;" : "+l"(acc) : "l"(a), "l"(b))

__device__ __forceinline__ void cp_async16(uint32_t s, const void* g) {
    asm volatile("cp.async.cg.shared.global [%0], [%1], 16;" :: "r"(s), "l"(g));
}
__device__ __forceinline__ void cp_async4(uint32_t s, const void* g) {
    asm volatile("cp.async.ca.shared.global [%0], [%1], 4;" :: "r"(s), "l"(g));
}
__device__ __forceinline__ void cp_commit() {
    asm volatile("cp.async.commit_group;");
}
__device__ __forceinline__ void cp_wait0() {
    asm volatile("cp.async.wait_group 0;" ::: "memory");
}
__device__ __forceinline__ void l2_prefetch(const void* g) {
    asm volatile("prefetch.global.L2 [%0];" :: "l"(g));
}

__device__ __forceinline__ void prefetch_tile(const float* __restrict__ weights,
                                              int n, int tile, float* swbuf, int tid)
{
    int base = tile * VPB;
    int nf = (n - base) * NJ;
    if (nf > WBUF) nf = WBUF;
    const float* g = weights + (size_t)base * NJ;   // base % 4 == 0 -> 16B aligned
    uint32_t sbase = (uint32_t)__cvta_generic_to_shared(swbuf);
    int n4 = nf >> 2;
    for (int i = tid; i < n4; i += TPB)
        cp_async16(sbase + i * 16, g + i * 4);
    for (int i = (n4 << 2) + tid; i < nf; i += TPB)   // tail (not taken for this n)
        cp_async4(sbase + i * 4, g + i);
}

__global__ void __launch_bounds__(TPB)
lbs_kernel(const float* __restrict__ points,
           const float* __restrict__ weights,
           const float* __restrict__ SE3,
           float* __restrict__ out,
           int n, int ntiles)
{
    extern __shared__ __align__(16) float smem[];
    float*   sw = smem;
    double2* sm = (double2*)(smem + WBUF);   // SE3 rows 0..2 as packed f32x2 pairs

    const int tid = threadIdx.x;

    // --- Stage SE3 once (rows 0..2 of each joint; each row is one float4) ---
    {
        const float4* g = (const float4*)SE3;
        for (int idx = tid; idx < NJ * 3; idx += TPB) {
            int j = idx / 3;
            int r = idx - j * 3;
            float4 v = g[j * 4 + r];
            *(float4*)(&sm[idx]) = v;
        }
    }

    for (int tile = blockIdx.x; tile < ntiles; tile += GRID) {
        // Issue this tile's smem fill; cross-CTA overlap hides most of it, and
        // (after the first lap) the lines are already L2-resident from prefetch.
        prefetch_tile(weights, n, tile, sw, tid);
        cp_commit();

        // L2-prefetch NEXT tile's weight lines (220 x 128B): zero smem cost,
        // ~4 instrs/thread, one full tile period of lead time.
        {
            int nt = tile + GRID;
            if (nt < ntiles) {
                const char* g = (const char*)(weights + (size_t)nt * VPB * NJ);
                size_t maxb = ((size_t)n - (size_t)nt * VPB) * NJ * 4;
                size_t tb = (size_t)WBUF * 4;
                if (tb > maxb) tb = maxb;
                for (int l = tid; l < TILE_LINES; l += TPB) {
                    size_t off = (size_t)l * 128;
                    if (off < tb) l2_prefetch(g + off);
                }
            }
        }

        const int base = tile * VPB;
        const int v0 = base + tid;
        const int v1 = base + TPB + tid;
        const bool has0 = (v0 < n);
        const bool has1 = (v1 < n);

        // Point loads fly during the cp.async wait
        float px0 = 0.f, py0 = 0.f, pz0 = 0.f, px1 = 0.f, py1 = 0.f, pz1 = 0.f;
        if (has0) {
            px0 = __ldg(&points[(size_t)v0 * 3 + 0]);
            py0 = __ldg(&points[(size_t)v0 * 3 + 1]);
            pz0 = __ldg(&points[(size_t)v0 * 3 + 2]);
        }
        if (has1) {
            px1 = __ldg(&points[(size_t)v1 * 3 + 0]);
            py1 = __ldg(&points[(size_t)v1 * 3 + 1]);
            pz1 = __ldg(&points[(size_t)v1 * 3 + 2]);
        }

        cp_wait0();
        __syncthreads();   // tile visible to both warps (also orders SE3 staging on iter 0)

        if (has0) {
            // Packed accumulators for blended 3x4 matrices of both vertices
            unsigned long long a0 = 0ull, a1 = 0ull, a2 = 0ull, a3 = 0ull, a4 = 0ull, a5 = 0ull;
            unsigned long long b0 = 0ull, b1 = 0ull, b2 = 0ull, b3 = 0ull, b4 = 0ull, b5 = 0ull;

            const float* wrowA = sw + tid * NJ;          // lane stride 55 words -> conflict-free
            const float* wrowB = sw + (tid + TPB) * NJ;

            #pragma unroll
            for (int j = 0; j < NJ; ++j) {
                float wA = wrowA[j];
                float wB = wrowB[j];
                unsigned long long wA2, wB2;
                asm("mov.b64 %0, {%1, %1};" : "=l"(wA2) : "r"(__float_as_uint(wA)));
                asm("mov.b64 %0, {%1, %1};" : "=l"(wB2) : "r"(__float_as_uint(wB)));

                double2 r0 = sm[j * 3 + 0];   // LDS.128 broadcast, shared by both vertices
                double2 r1 = sm[j * 3 + 1];
                double2 r2 = sm[j * 3 + 2];
                unsigned long long m01 = __double_as_longlong(r0.x);
                unsigned long long m23 = __double_as_longlong(r0.y);
                unsigned long long m45 = __double_as_longlong(r1.x);
                unsigned long long m67 = __double_as_longlong(r1.y);
                unsigned long long m89 = __double_as_longlong(r2.x);
                unsigned long long mAB = __double_as_longlong(r2.y);

                FMA_F32X2(a0, wA2, m01);  FMA_F32X2(b0, wB2, m01);
                FMA_F32X2(a1, wA2, m23);  FMA_F32X2(b1, wB2, m23);
                FMA_F32X2(a2, wA2, m45);  FMA_F32X2(b2, wB2, m45);
                FMA_F32X2(a3, wA2, m67);  FMA_F32X2(b3, wB2, m67);
                FMA_F32X2(a4, wA2, m89);  FMA_F32X2(b4, wB2, m89);
                FMA_F32X2(a5, wA2, mAB);  FMA_F32X2(b5, wB2, mAB);
            }

            // --- Vertex 0 epilogue ---
            {
                float A00, A01, A02, A03, A10, A11, A12, A13, A20, A21, A22, A23;
                asm("mov.b64 {%0, %1}, %2;" : "=f"(A00), "=f"(A01) : "l"(a0));
                asm("mov.b64 {%0, %1}, %2;" : "=f"(A02), "=f"(A03) : "l"(a1));
                asm("mov.b64 {%0, %1}, %2;" : "=f"(A10), "=f"(A11) : "l"(a2));
                asm("mov.b64 {%0, %1}, %2;" : "=f"(A12), "=f"(A13) : "l"(a3));
                asm("mov.b64 {%0, %1}, %2;" : "=f"(A20), "=f"(A21) : "l"(a4));
                asm("mov.b64 {%0, %1}, %2;" : "=f"(A22), "=f"(A23) : "l"(a5));
                out[(size_t)v0 * 3 + 0] = fmaf(A00, px0, fmaf(A01, py0, fmaf(A02, pz0, A03)));
                out[(size_t)v0 * 3 + 1] = fmaf(A10, px0, fmaf(A11, py0, fmaf(A12, pz0, A13)));
                out[(size_t)v0 * 3 + 2] = fmaf(A20, px0, fmaf(A21, py0, fmaf(A22, pz0, A23)));
            }

            // --- Vertex 1 epilogue ---
            if (has1) {
                float A00, A01, A02, A03, A10, A11, A12, A13, A20, A21, A22, A23;
                asm("mov.b64 {%0, %1}, %2;" : "=f"(A00), "=f"(A01) : "l"(b0));
                asm("mov.b64 {%0, %1}, %2;" : "=f"(A02), "=f"(A03) : "l"(b1));
                asm("mov.b64 {%0, %1}, %2;" : "=f"(A10), "=f"(A11) : "l"(b2));
                asm("mov.b64 {%0, %1}, %2;" : "=f"(A12), "=f"(A13) : "l"(b3));
                asm("mov.b64 {%0, %1}, %2;" : "=f"(A20), "=f"(A21) : "l"(b4));
                asm("mov.b64 {%0, %1}, %2;" : "=f"(A22), "=f"(A23) : "l"(b5));
                out[(size_t)v1 * 3 + 0] = fmaf(A00, px1, fmaf(A01, py1, fmaf(A02, pz1, A03)));
                out[(size_t)v1 * 3 + 1] = fmaf(A10, px1, fmaf(A11, py1, fmaf(A12, pz1, A13)));
                out[(size_t)v1 * 3 + 2] = fmaf(A20, px1, fmaf(A21, py1, fmaf(A22, pz1, A23)));
            }
        }

        __syncthreads();   // both warps done reading sw before next iteration overwrites
    }
}

extern "C" void kernel_launch(void* const* d_in, const int* in_sizes, int n_in,
                              void* d_out, int out_size)
{
    const float* points  = (const float*)d_in[0];   // [n,3]
    const float* weights = (const float*)d_in[1];   // [n,55]
    const float* SE3     = (const float*)d_in[2];   // [55,4,4]
    float* out = (float*)d_out;

    int n = in_sizes[0] / 3;
    int ntiles = (n + VPB - 1) / VPB;

    cudaFuncSetAttribute(lbs_kernel, cudaFuncAttributeMaxDynamicSharedMemorySize, SMEM_BYTES);

    int grid = (ntiles < GRID) ? ntiles : GRID;
    lbs_kernel<<<grid, TPB, SMEM_BYTES>>>(points, weights, SE3, out, n, ntiles);
}